// round 7
// baseline (speedup 1.0000x reference)
#include <cuda_runtime.h>
#include <cstdint>

// Scratch: pooled means [8 batches x 128 channels]
__device__ float g_pooled[1024];

// Hierarchical completion counters (distinct 128B lines)
struct __align__(128) PadCnt { unsigned int v; unsigned int pad[31]; };
__device__ PadCnt g_cnt_part[32];
__device__ unsigned int g_cnt_final = 0;

__device__ __forceinline__ float4 ldg_nc_256(const float4* p) {
    float4 v;
    asm volatile("ld.global.nc.L2::256B.v4.f32 {%0,%1,%2,%3}, [%4];"
                 : "=f"(v.x), "=f"(v.y), "=f"(v.z), "=f"(v.w)
                 : "l"(p));
    return v;
}

__device__ __forceinline__ void prefetch_l2(const void* p) {
    asm volatile("prefetch.global.L2 [%0];" :: "l"(p));
}

// 1024 blocks x 256 threads; one 256x256 plane per block (near-perfect wave
// balance: 6.92 waves on 148 SMs). Phase A: pooled[p] = mean over even h, even w.
// Phase B (globally-last block): tiny MLP.
__global__ __launch_bounds__(256) void fused_kernel(const float* __restrict__ bsrc,
                                                    const float* __restrict__ fc1_w,
                                                    const float* __restrict__ fc2_w,
                                                    float* __restrict__ out) {
    const int blk = blockIdx.x;                    // 0..1023 = b*128 + c (plane id)
    const int tid = threadIdx.x;

    // Warm L2 with the FC weights so the Phase-B tail hits L2, not DRAM.
    // fc1_w: 32*128*4 = 16 KB, fc2_w: 128*32*4 = 16 KB -> 256 lines total.
    if (blk == 0) {
        prefetch_l2((const char*)fc1_w + tid * 64);     // 256*64 = 16 KB
        prefetch_l2((const char*)fc2_w + tid * 64);
    }

    // ---------- Phase A ----------
    const float4* __restrict__ base =
        reinterpret_cast<const float4*>(bsrc) + (size_t)blk * 16384;   // plane = 16384 f4

    // 128 even rows * 64 f4/row = 8192 f4 per plane; 32 per thread, 8-deep batches.
    float acc = 0.0f;
    #pragma unroll
    for (int kk = 0; kk < 32; kk += 8) {
        float4 v[8];
        #pragma unroll
        for (int u = 0; u < 8; ++u) {
            const int i  = tid + (kk + u) * 256;
            const int r  = i >> 6;                 // even-row index 0..127
            const int c4 = i & 63;
            v[u] = ldg_nc_256(base + ((r << 7) + c4));   // 2r * 64 = r*128
        }
        float s0 = 0.f, s1 = 0.f, s2 = 0.f, s3 = 0.f;
        #pragma unroll
        for (int u = 0; u < 8; u += 4) {
            s0 += v[u + 0].x + v[u + 0].z;
            s1 += v[u + 1].x + v[u + 1].z;
            s2 += v[u + 2].x + v[u + 2].z;
            s3 += v[u + 3].x + v[u + 3].z;
        }
        acc += (s0 + s1) + (s2 + s3);
    }

    #pragma unroll
    for (int off = 16; off > 0; off >>= 1)
        acc += __shfl_xor_sync(0xFFFFFFFFu, acc, off);

    __shared__ float warp_sums[8];
    __shared__ int is_last;
    if ((tid & 31) == 0) warp_sums[tid >> 5] = acc;
    if (tid == 0) is_last = 0;
    __syncthreads();

    if (tid == 0) {
        float s = warp_sums[0];
        #pragma unroll
        for (int w = 1; w < 8; ++w) s += warp_sums[w];
        g_pooled[blk] = s * (1.0f / 65536.0f);
        __threadfence();

        // Two-level completion: 32 blocks per partition counter, then final.
        unsigned int old = atomicAdd(&g_cnt_part[blk & 31].v, 1u);
        if (old == 31u) {
            unsigned int old2 = atomicAdd(&g_cnt_final, 1u);
            if (old2 == 31u) {
                g_cnt_final = 0u;
                #pragma unroll
                for (int p = 0; p < 32; ++p) g_cnt_part[p].v = 0u;
                is_last = 1;
            }
        }
    }
    __syncthreads();
    if (!is_last) return;

    // ---------- Phase B: tiny MLP (globally-last block only) ----------
    __shared__ __align__(16) float sp[1024];       // pooled [8][128]
    __shared__ __align__(16) float sh[256];        // hidden [8][32]

    #pragma unroll
    for (int k = 0; k < 4; ++k) {
        const int i = tid + k * 256;
        sp[i] = __ldcg(&g_pooled[i]);              // L2-hot, bypass L1
    }
    __syncthreads();

    // hidden[b][j] = relu( sum_c pooled[b][c] * fc1_w[j][c] )
    {
        const int j  = tid & 31;                   // hidden unit
        const int bb = tid >> 5;                   // batch
        const float4* __restrict__ w4 = reinterpret_cast<const float4*>(fc1_w) + j * 32;
        const float4* __restrict__ p4 = reinterpret_cast<const float4*>(sp) + bb * 32;
        float s = 0.0f;
        #pragma unroll
        for (int k = 0; k < 32; ++k) {
            float4 w = __ldg(&w4[k]);
            float4 p = p4[k];
            s = fmaf(w.x, p.x, s);
            s = fmaf(w.y, p.y, s);
            s = fmaf(w.z, p.z, s);
            s = fmaf(w.w, p.w, s);
        }
        sh[tid] = fmaxf(s, 0.0f);
    }
    __syncthreads();

    // out[b][c] = sum_j hidden[b][j] * fc2_w[c][j]
    #pragma unroll
    for (int k = 0; k < 4; ++k) {
        const int idx = tid + k * 256;             // b*128 + c
        const int bb  = idx >> 7;
        const int c   = idx & 127;
        const float4* __restrict__ w4 = reinterpret_cast<const float4*>(fc2_w) + c * 8;
        const float4* __restrict__ h4 = reinterpret_cast<const float4*>(sh) + bb * 8;
        float s = 0.0f;
        #pragma unroll
        for (int q = 0; q < 8; ++q) {
            float4 w = __ldg(&w4[q]);
            float4 h = h4[q];
            s = fmaf(w.x, h.x, s);
            s = fmaf(w.y, h.y, s);
            s = fmaf(w.z, h.z, s);
            s = fmaf(w.w, h.w, s);
        }
        out[idx] = s;
    }
}

extern "C" void kernel_launch(void* const* d_in, const int* in_sizes, int n_in,
                              void* d_out, int out_size) {
    // metadata order: a, b, attn_w, attn_b, fc1_w, fc2_w
    const float* bsrc  = (const float*)d_in[1];
    const float* fc1_w = (const float*)d_in[4];
    const float* fc2_w = (const float*)d_in[5];
    float* out = (float*)d_out;

    fused_kernel<<<1024, 256>>>(bsrc, fc1_w, fc2_w, out);
}

// round 8
// speedup vs baseline: 1.2344x; 1.2344x over previous
#include <cuda_runtime.h>
#include <cstdint>

// Scratch: pooled means [8 batches x 128 channels]
__device__ float g_pooled[1024];

// Per-batch completion counters on distinct 128B L2 lines.
struct __align__(128) PadCnt { unsigned int v; unsigned int pad[31]; };
__device__ PadCnt g_cnt_batch[8];

__device__ __forceinline__ float4 ldg_nc_256(const float4* p) {
    float4 v;
    asm volatile("ld.global.nc.L2::256B.v4.f32 {%0,%1,%2,%3}, [%4];"
                 : "=f"(v.x), "=f"(v.y), "=f"(v.z), "=f"(v.w)
                 : "l"(p));
    return v;
}

__device__ __forceinline__ void prefetch_l2(const void* p) {
    asm volatile("prefetch.global.L2 [%0];" :: "l"(p));
}

// 1024 blocks x 256 threads; one 256x256 plane per block (blk = b*128 + c).
// Phase A: pooled[blk] = mean over even h, even w of plane blk.
// Phase B: the 128th-arriving block OF EACH BATCH computes that batch's
// fc1 -> relu -> fc2 and writes out[b, 0..127]. No global barrier needed:
// out[b,:] depends only on pooled[b,:].
__global__ __launch_bounds__(256) void fused_kernel(const float* __restrict__ bsrc,
                                                    const float* __restrict__ fc1_w,
                                                    const float* __restrict__ fc2_w,
                                                    float* __restrict__ out) {
    const int blk = blockIdx.x;                    // 0..1023
    const int tid = threadIdx.x;
    const int bb  = blk >> 7;                      // batch 0..7

    // Warm L2 with FC weights (16 KB each) so batch tails hit L2, not DRAM.
    if (blk == 0) {
        prefetch_l2((const char*)fc1_w + tid * 64);
        prefetch_l2((const char*)fc2_w + tid * 64);
    }

    // ---------- Phase A ----------
    const float4* __restrict__ base =
        reinterpret_cast<const float4*>(bsrc) + (size_t)blk * 16384;

    float acc = 0.0f;
    #pragma unroll
    for (int kk = 0; kk < 32; kk += 8) {
        float4 v[8];
        #pragma unroll
        for (int u = 0; u < 8; ++u) {
            const int i  = tid + (kk + u) * 256;
            const int r  = i >> 6;                 // even-row index 0..127
            const int c4 = i & 63;
            v[u] = ldg_nc_256(base + ((r << 7) + c4));
        }
        float s0 = 0.f, s1 = 0.f, s2 = 0.f, s3 = 0.f;
        #pragma unroll
        for (int u = 0; u < 8; u += 4) {
            s0 += v[u + 0].x + v[u + 0].z;
            s1 += v[u + 1].x + v[u + 1].z;
            s2 += v[u + 2].x + v[u + 2].z;
            s3 += v[u + 3].x + v[u + 3].z;
        }
        acc += (s0 + s1) + (s2 + s3);
    }

    #pragma unroll
    for (int off = 16; off > 0; off >>= 1)
        acc += __shfl_xor_sync(0xFFFFFFFFu, acc, off);

    __shared__ float warp_sums[8];
    __shared__ int is_batch_last;
    if ((tid & 31) == 0) warp_sums[tid >> 5] = acc;
    if (tid == 0) is_batch_last = 0;
    __syncthreads();

    if (tid == 0) {
        float s = warp_sums[0];
        #pragma unroll
        for (int w = 1; w < 8; ++w) s += warp_sums[w];
        g_pooled[blk] = s * (1.0f / 65536.0f);
        __threadfence();                           // publish before counting

        unsigned int old = atomicAdd(&g_cnt_batch[bb].v, 1u);
        if (old == 127u) {
            g_cnt_batch[bb].v = 0u;                // reset for next graph replay
            is_batch_last = 1;
        }
    }
    __syncthreads();
    if (!is_batch_last) return;

    // ---------- Phase B: this batch's slice of the MLP ----------
    __shared__ __align__(16) float sp[128];        // pooled[bb][0..127]
    __shared__ __align__(16) float sh[32];         // hidden[bb][0..31]

    if (tid < 128) sp[tid] = __ldcg(&g_pooled[(bb << 7) + tid]);
    __syncthreads();

    // hidden[j] = relu( sum_c sp[c] * fc1_w[j][c] ), 8 threads per unit j.
    {
        const int j = tid >> 3;                    // hidden unit 0..31
        const int k = tid & 7;                     // sub-lane 0..7, 16 channels each
        const float4* __restrict__ w4 = reinterpret_cast<const float4*>(fc1_w) + j * 32 + k * 4;
        const float4* __restrict__ p4 = reinterpret_cast<const float4*>(sp) + k * 4;
        float s = 0.0f;
        #pragma unroll
        for (int q = 0; q < 4; ++q) {
            float4 w = __ldg(&w4[q]);
            float4 p = p4[q];
            s = fmaf(w.x, p.x, s);
            s = fmaf(w.y, p.y, s);
            s = fmaf(w.z, p.z, s);
            s = fmaf(w.w, p.w, s);
        }
        // Reduce over the 8 sub-lanes (within one warp: groups of 8 lanes)
        s += __shfl_xor_sync(0xFFFFFFFFu, s, 4);
        s += __shfl_xor_sync(0xFFFFFFFFu, s, 2);
        s += __shfl_xor_sync(0xFFFFFFFFu, s, 1);
        if (k == 0) sh[j] = fmaxf(s, 0.0f);
    }
    __syncthreads();

    // out[bb*128 + c] = sum_j sh[j] * fc2_w[c][j]; threads 0..127, one output each.
    if (tid < 128) {
        const float4* __restrict__ w4 = reinterpret_cast<const float4*>(fc2_w) + tid * 8;
        const float4* __restrict__ h4 = reinterpret_cast<const float4*>(sh);
        float s = 0.0f;
        #pragma unroll
        for (int q = 0; q < 8; ++q) {
            float4 w = __ldg(&w4[q]);
            float4 h = h4[q];
            s = fmaf(w.x, h.x, s);
            s = fmaf(w.y, h.y, s);
            s = fmaf(w.z, h.z, s);
            s = fmaf(w.w, h.w, s);
        }
        out[(bb << 7) + tid] = s;
    }
}

extern "C" void kernel_launch(void* const* d_in, const int* in_sizes, int n_in,
                              void* d_out, int out_size) {
    // metadata order: a, b, attn_w, attn_b, fc1_w, fc2_w
    const float* bsrc  = (const float*)d_in[1];
    const float* fc1_w = (const float*)d_in[4];
    const float* fc2_w = (const float*)d_in[5];
    float* out = (float*)d_out;

    fused_kernel<<<1024, 256>>>(bsrc, fc1_w, fc2_w, out);
}